// round 1
// baseline (speedup 1.0000x reference)
#include <cuda_runtime.h>

#define N_USERS 8192
#define DIM 128
#define E_PAIRS 262144
#define K_CAND 131072
#define TOT (E_PAIRS + K_CAND)   /* 393216 */
#define COS_THRESH 0.3f
#define TAU_F 0.2f

#define TM 64
#define TN 128
#define JSPLIT 2
#define JRANGE (N_USERS / JSPLIT)    /* 4096 */
#define NCHUNK (JRANGE / TN)         /* 32 */
#define CAP 64
#define ASTRIDE 68
#define BSTRIDE 132
#define SMEM_FLOATS (DIM*ASTRIDE + DIM*BSTRIDE)
#define SMEM_BYTES (SMEM_FLOATS*4)

// ---- device scratch (static; no allocations allowed) ----
__device__ float    g_u[N_USERS*DIM];                 // normalized embeddings (4MB)
__device__ float    g_AB[N_USERS*4];                  // per-user partial logits A0,A1,B0,B1
__device__ unsigned g_excl[N_USERS*N_USERS/32];       // exclusion bitmap (8MB)
__device__ int      g_cnt[N_USERS*JSPLIT];            // per (row, jblock) candidate count
__device__ int      g_off[N_USERS*JSPLIT];            // exclusive prefix
__device__ int      g_cjbuf[N_USERS*JSPLIT*CAP];      // bucket: col indices (4MB)
__device__ float    g_cvbuf[N_USERS*JSPLIT*CAP];      // bucket: cos values  (4MB)
__device__ int      g_ci[K_CAND];
__device__ int      g_cj[K_CAND];
__device__ float    g_cv[K_CAND];

// ---------------- clear exclusion bitmap ----------------
__global__ void k_clear() {
    int idx = blockIdx.x * blockDim.x + threadIdx.x;
    int stride = gridDim.x * blockDim.x;
    for (int i = idx; i < N_USERS*N_USERS/32; i += stride) g_excl[i] = 0u;
}

// ---------------- set bits for nonzero_idx pairs ----------------
__global__ void k_setbits(const int* __restrict__ nz) {
    int t = blockIdx.x * blockDim.x + threadIdx.x;
    if (t < E_PAIRS) {
        int i = nz[2*t];
        int j = nz[2*t+1];
        unsigned lin = (unsigned)i * N_USERS + (unsigned)j;
        atomicOr(&g_excl[lin >> 5], 1u << (lin & 31u));
    }
}

// ---------------- normalize rows + partial logits ----------------
__device__ __forceinline__ float blockSum128(float v) {
    __shared__ float sh[4];
    __syncthreads();                   // protect sh from previous call's readers
    #pragma unroll
    for (int o = 16; o; o >>= 1) v += __shfl_down_sync(0xffffffffu, v, o);
    if ((threadIdx.x & 31) == 0) sh[threadIdx.x >> 5] = v;
    __syncthreads();
    return sh[0] + sh[1] + sh[2] + sh[3];
}

__global__ void k_prep(const float* __restrict__ emb, const float* __restrict__ W) {
    int row = blockIdx.x;
    int t = threadIdx.x;             // 0..127
    float e = emb[row*DIM + t];

    float sumsq = blockSum128(e*e);
    float nrm = __fsqrt_rn(sumsq);
    float den = fmaxf(nrm, 1e-12f);
    g_u[row*DIM + t] = __fdiv_rn(e, den);

    float a0 = blockSum128(e * W[0*256 + t]);
    float a1 = blockSum128(e * W[1*256 + t]);
    float b0 = blockSum128(e * W[0*256 + 128 + t]);
    float b1 = blockSum128(e * W[1*256 + 128 + t]);
    if (t == 0) {
        g_AB[row*4+0] = a0;
        g_AB[row*4+1] = a1;
        g_AB[row*4+2] = b0;
        g_AB[row*4+3] = b1;
    }
}

// ---------------- fill candidate defaults ----------------
__global__ void k_fill() {
    int t = blockIdx.x * blockDim.x + threadIdx.x;
    if (t < K_CAND) { g_ci[t] = 0; g_cj[t] = 0; g_cv[t] = -1.0f; }
}

// ---------------- masked cosine GEMM + ordered compaction ----------------
__global__ void __launch_bounds__(256) k_gemm() {
    extern __shared__ float smem[];
    float* Ash = smem;                       // [k][m], stride ASTRIDE
    float* Bsh = smem + DIM*ASTRIDE;         // [k][n], stride BSTRIDE; reused as stage [m][n]

    int tid = threadIdx.x;
    int tx = tid & 31;          // column group (n/4)
    int ty = tid >> 5;          // row group (m/8), == warp id
    int rg = blockIdx.x >> 1;
    int jb = blockIdx.x & 1;
    int row0 = rg * TM;
    int jbase = jb * JRANGE;

    // load A tile (64 rows x 128 k), transposed into [k][m]
    for (int i = tid; i < 32*TM; i += 256) {
        int m  = i >> 5;
        int k4 = i & 31;
        float4 v = *(const float4*)&g_u[(row0+m)*DIM + k4*4];
        Ash[(k4*4+0)*ASTRIDE + m] = v.x;
        Ash[(k4*4+1)*ASTRIDE + m] = v.y;
        Ash[(k4*4+2)*ASTRIDE + m] = v.z;
        Ash[(k4*4+3)*ASTRIDE + m] = v.w;
    }

    int cnt[8];
    #pragma unroll
    for (int r = 0; r < 8; r++) cnt[r] = 0;

    for (int jc = 0; jc < NCHUNK; jc++) {
        int col0 = jbase + jc*TN;
        __syncthreads();   // previous scan done (Bsh free); Ash ready on first iter

        // load B tile (128 cols x 128 k), transposed into [k][n] (coalesced global)
        for (int i = tid; i < 32*TN; i += 256) {
            int n  = i >> 5;
            int k4 = i & 31;
            float4 v = *(const float4*)&g_u[(col0+n)*DIM + k4*4];
            Bsh[(k4*4+0)*BSTRIDE + n] = v.x;
            Bsh[(k4*4+1)*BSTRIDE + n] = v.y;
            Bsh[(k4*4+2)*BSTRIDE + n] = v.z;
            Bsh[(k4*4+3)*BSTRIDE + n] = v.w;
        }
        __syncthreads();

        float acc[8][4];
        #pragma unroll
        for (int r = 0; r < 8; r++)
            #pragma unroll
            for (int c = 0; c < 4; c++) acc[r][c] = 0.0f;

        const float* BP = Bsh + tx*4;
        const float* AP = Ash + ty*8;
        #pragma unroll 4
        for (int k = 0; k < DIM; k++) {
            float4 b4 = *(const float4*)(BP + k*BSTRIDE);
            float4 a0 = *(const float4*)(AP + k*ASTRIDE);
            float4 a1 = *(const float4*)(AP + k*ASTRIDE + 4);
            float a[8] = {a0.x,a0.y,a0.z,a0.w,a1.x,a1.y,a1.z,a1.w};
            float b[4] = {b4.x,b4.y,b4.z,b4.w};
            #pragma unroll
            for (int r = 0; r < 8; r++)
                #pragma unroll
                for (int c = 0; c < 4; c++)
                    acc[r][c] = fmaf(a[r], b[c], acc[r][c]);
        }
        __syncthreads();   // all FMAs read Bsh; now safe to overwrite with stage

        // stage cos tile [m][n] row-major (stride TN)
        #pragma unroll
        for (int r = 0; r < 8; r++) {
            float4 s = make_float4(acc[r][0], acc[r][1], acc[r][2], acc[r][3]);
            *(float4*)&Bsh[(ty*8+r)*TN + tx*4] = s;
        }
        __syncthreads();

        // ordered scan: warp ty owns rows ty*8 .. ty*8+7
        #pragma unroll
        for (int r = 0; r < 8; r++) {
            int m = ty*8 + r;
            int ig = row0 + m;
            int c = cnt[r];
            #pragma unroll
            for (int rd = 0; rd < 4; rd++) {
                int n = rd*32 + tx;
                float v = Bsh[m*TN + n];
                int j = col0 + n;
                bool p = (v > COS_THRESH) && (j != ig);
                if (p) {
                    unsigned lin = (unsigned)ig * N_USERS + (unsigned)j;
                    unsigned word = g_excl[lin >> 5];
                    if ((word >> (lin & 31u)) & 1u) p = false;
                }
                unsigned mask = __ballot_sync(0xffffffffu, p);
                if (p) {
                    int pos = c + __popc(mask & ((1u << tx) - 1u));
                    if (pos < CAP) {
                        int base = (ig*JSPLIT + jb)*CAP;
                        g_cjbuf[base + pos] = j;
                        g_cvbuf[base + pos] = v;
                    }
                }
                c += __popc(mask);
            }
            cnt[r] = c;
        }
    }

    if (tx == 0) {
        #pragma unroll
        for (int r = 0; r < 8; r++) {
            int ig = row0 + ty*8 + r;
            g_cnt[ig*JSPLIT + jb] = cnt[r] < CAP ? cnt[r] : CAP;
        }
    }
}

// ---------------- prefix sum over 16384 counts ----------------
__global__ void k_scanp() {
    __shared__ int partial[256];
    int t = threadIdx.x;
    int base = t * 64;
    int s = 0;
    for (int i = 0; i < 64; i++) s += g_cnt[base + i];
    partial[t] = s;
    __syncthreads();
    for (int d = 1; d < 256; d <<= 1) {
        int v = (t >= d) ? partial[t-d] : 0;
        __syncthreads();
        partial[t] += v;
        __syncthreads();
    }
    int off = (t == 0) ? 0 : partial[t-1];
    for (int i = 0; i < 64; i++) {
        g_off[base + i] = off;
        off += g_cnt[base + i];
    }
}

// ---------------- emit candidates in global row-major order ----------------
__global__ void k_emit() {
    int g = blockIdx.x * blockDim.x + threadIdx.x;
    if (g >= N_USERS*JSPLIT) return;
    int c = g_cnt[g];
    int o = g_off[g];
    int i = g / JSPLIT;
    int base = g * CAP;
    for (int s = 0; s < c; s++) {
        int pos = o + s;
        if (pos < K_CAND) {
            g_ci[pos] = i;
            g_cj[pos] = g_cjbuf[base + s];
            g_cv[pos] = g_cvbuf[base + s];
        }
    }
}

// ---------------- gumbel gate + outputs ----------------
__global__ void k_final(const int* __restrict__ nz, const float* __restrict__ gn,
                        const float* __restrict__ bvec, float* __restrict__ out) {
    int t = blockIdx.x * blockDim.x + threadIdx.x;
    if (t >= TOT) return;
    int i, j; float wgt;
    if (t < E_PAIRS) {
        i = nz[2*t]; j = nz[2*t+1]; wgt = 1.0f;
    } else {
        int c = t - E_PAIRS;
        i = g_ci[c]; j = g_cj[c];
        wgt = fmaxf(g_cv[c], 0.0f);
    }
    float l0 = g_AB[i*4+0] + g_AB[j*4+2] + bvec[0];
    float l1 = g_AB[i*4+1] + g_AB[j*4+3] + bvec[1];
    float z0 = (l0 + gn[2*t])   / TAU_F;
    float z1 = (l1 + gn[2*t+1]) / TAU_F;
    float mx = fmaxf(z0, z1);
    float e0 = expf(z0 - mx), e1 = expf(z1 - mx);
    float s0 = e0 / (e0 + e1);
    float h0 = (z1 > z0) ? 0.0f : 1.0f;     // argmax ties -> index 0
    float r = (h0 + s0) - s0;                // straight-through forward value
    float w = r * wgt;

    out[t]          = w;                     // gumbel_01
    out[TOT + t]    = w;                     // gumbel_retain_w[0:TOT]
    out[2*TOT + t]  = w;                     // gumbel_retain_w[TOT:2*TOT]
    out[3*TOT + 2*t]     = (float)i;         // pair_idx
    out[3*TOT + 2*t + 1] = (float)j;
}

// ---------------- launcher ----------------
extern "C" void kernel_launch(void* const* d_in, const int* in_sizes, int n_in,
                              void* d_out, int out_size) {
    const float* emb = (const float*)d_in[0];   // user_emb (8192,128)
    const float* W   = (const float*)d_in[1];   // W (2,256)
    const float* b   = (const float*)d_in[2];   // b (2,)
    const float* gn  = (const float*)d_in[3];   // gumbel_noise (393216,2)
    const int*   nz  = (const int*)d_in[4];     // nonzero_idx (262144,2)
    float* out = (float*)d_out;

    cudaFuncSetAttribute(k_gemm, cudaFuncAttributeMaxDynamicSharedMemorySize, SMEM_BYTES);

    k_clear  <<<2048, 256>>>();
    k_setbits<<<(E_PAIRS+255)/256, 256>>>(nz);
    k_prep   <<<N_USERS, 128>>>(emb, W);
    k_fill   <<<(K_CAND+255)/256, 256>>>();
    k_gemm   <<<(N_USERS/TM)*JSPLIT, 256, SMEM_BYTES>>>();
    k_scanp  <<<1, 256>>>();
    k_emit   <<<(N_USERS*JSPLIT+127)/128, 128>>>();
    k_final  <<<(TOT+255)/256, 256>>>(nz, gn, b, out);
}

// round 2
// speedup vs baseline: 1.7226x; 1.7226x over previous
#include <cuda_runtime.h>

#define N_USERS 8192
#define DIM 128
#define E_PAIRS 262144
#define K_CAND 131072
#define TOT (E_PAIRS + K_CAND)   /* 393216 */
#define COS_THRESH 0.3f
#define TAU_F 0.2f

#define TILE 128
#define NB (N_USERS / TILE)          /* 64 tile-blocks */
#define NPAIR (NB * (NB + 1) / 2)    /* 2080 */
#define NBUK (N_USERS * NB)          /* 524288 buckets */
#define CAP 16
#define AST 132
#define BST 132
#define SMEM_FLOATS (DIM*AST + DIM*BST)
#define SMEM_BYTES (SMEM_FLOATS*4)   /* 135168 */

// ---- device scratch (static; no allocations allowed) ----
__device__ float    g_u[N_USERS*DIM];                 // normalized embeddings (4MB)
__device__ float    g_AB[N_USERS*4];                  // per-user partial logits A0,A1,B0,B1
__device__ unsigned g_excl[N_USERS*N_USERS/32];       // exclusion bitmap (8MB)
__device__ int      g_cnt[NBUK];                      // per (row, colblock) count
__device__ int      g_part[512];                      // block partials for scan
__device__ int      g_cjbuf[NBUK*CAP];                // bucket: col indices (32MB)
__device__ float    g_cvbuf[NBUK*CAP];                // bucket: cos values  (32MB)
__device__ int      g_ci[K_CAND];
__device__ int      g_cj[K_CAND];
__device__ float    g_cv[K_CAND];

// ---------------- packed f32x2 helpers ----------------
__device__ __forceinline__ unsigned long long pack2(float lo, float hi) {
    unsigned long long r;
    asm("mov.b64 %0, {%1, %2};" : "=l"(r) : "f"(lo), "f"(hi));
    return r;
}
__device__ __forceinline__ unsigned long long dup2(float v) {
    unsigned long long r;
    asm("mov.b64 %0, {%1, %1};" : "=l"(r) : "f"(v));
    return r;
}
__device__ __forceinline__ void fma2(unsigned long long& d, unsigned long long a,
                                     unsigned long long b) {
    asm("fma.rn.f32x2 %0, %1, %2, %3;" : "=l"(d) : "l"(a), "l"(b), "l"(d));
}
__device__ __forceinline__ void unpack2(unsigned long long v, float& lo, float& hi) {
    asm("mov.b64 {%0, %1}, %2;" : "=f"(lo), "=f"(hi) : "l"(v));
}

// ---------------- clear exclusion bitmap ----------------
__global__ void k_clear() {
    int idx = blockIdx.x * blockDim.x + threadIdx.x;
    int stride = gridDim.x * blockDim.x;
    for (int i = idx; i < N_USERS*N_USERS/32; i += stride) g_excl[i] = 0u;
}

// ---------------- set bits for nonzero_idx pairs ----------------
__global__ void k_setbits(const int* __restrict__ nz) {
    int t = blockIdx.x * blockDim.x + threadIdx.x;
    if (t < E_PAIRS) {
        int i = nz[2*t];
        int j = nz[2*t+1];
        unsigned lin = (unsigned)i * N_USERS + (unsigned)j;
        atomicOr(&g_excl[lin >> 5], 1u << (lin & 31u));
    }
}

// ---------------- normalize rows + partial logits ----------------
__device__ __forceinline__ float blockSum128(float v) {
    __shared__ float sh[4];
    __syncthreads();
    #pragma unroll
    for (int o = 16; o; o >>= 1) v += __shfl_down_sync(0xffffffffu, v, o);
    if ((threadIdx.x & 31) == 0) sh[threadIdx.x >> 5] = v;
    __syncthreads();
    return sh[0] + sh[1] + sh[2] + sh[3];
}

__global__ void k_prep(const float* __restrict__ emb, const float* __restrict__ W) {
    int row = blockIdx.x;
    int t = threadIdx.x;             // 0..127
    float e = emb[row*DIM + t];

    float sumsq = blockSum128(e*e);
    float nrm = __fsqrt_rn(sumsq);
    float den = fmaxf(nrm, 1e-12f);
    g_u[row*DIM + t] = __fdiv_rn(e, den);

    float a0 = blockSum128(e * W[0*256 + t]);
    float a1 = blockSum128(e * W[1*256 + t]);
    float b0 = blockSum128(e * W[0*256 + 128 + t]);
    float b1 = blockSum128(e * W[1*256 + 128 + t]);
    if (t == 0) {
        g_AB[row*4+0] = a0;
        g_AB[row*4+1] = a1;
        g_AB[row*4+2] = b0;
        g_AB[row*4+3] = b1;
    }
}

// ---------------- fill candidate defaults ----------------
__global__ void k_fill() {
    int t = blockIdx.x * blockDim.x + threadIdx.x;
    if (t < K_CAND) { g_ci[t] = 0; g_cj[t] = 0; g_cv[t] = -1.0f; }
}

// ---------------- symmetric cosine GEMM (f32x2) + ordered bucket scan ----------------
__global__ void __launch_bounds__(256) k_gemm() {
    extern __shared__ float smem[];
    float* Ash = smem;                       // [k][m], stride AST
    float* Bsh = smem + DIM*AST;             // [k][n], stride BST; reused as stage [m][n]

    int tid = threadIdx.x;

    // decode upper-triangle pair (bi <= bj)
    int t = blockIdx.x;
    int bi = 0;
    while (t >= NB - bi) { t -= NB - bi; bi++; }
    int bj = bi + t;
    int row0 = bi * TILE;
    int col0 = bj * TILE;

    // load A tile (rows of bi), transposed into [k][m]
    for (int i = tid; i < 32*TILE; i += 256) {
        int m  = i >> 5;
        int k4 = i & 31;
        float4 v = *(const float4*)&g_u[(row0+m)*DIM + k4*4];
        Ash[(k4*4+0)*AST + m] = v.x;
        Ash[(k4*4+1)*AST + m] = v.y;
        Ash[(k4*4+2)*AST + m] = v.z;
        Ash[(k4*4+3)*AST + m] = v.w;
    }
    // load B tile (rows of bj as columns), transposed into [k][n]
    for (int i = tid; i < 32*TILE; i += 256) {
        int n  = i >> 5;
        int k4 = i & 31;
        float4 v = *(const float4*)&g_u[(col0+n)*DIM + k4*4];
        Bsh[(k4*4+0)*BST + n] = v.x;
        Bsh[(k4*4+1)*BST + n] = v.y;
        Bsh[(k4*4+2)*BST + n] = v.z;
        Bsh[(k4*4+3)*BST + n] = v.w;
    }
    __syncthreads();

    // 8x8 micro-tile per thread, packed f32x2 accumulation over column pairs
    int txc = tid & 15;          // col group: n0 = txc*8
    int tyc = tid >> 4;          // row group: m0 = tyc*8
    const float* AP = Ash + tyc*8;
    const float* BP = Bsh + txc*8;

    unsigned long long acc2[8][4];
    #pragma unroll
    for (int r = 0; r < 8; r++)
        #pragma unroll
        for (int c = 0; c < 4; c++) acc2[r][c] = 0ull;

    #pragma unroll 2
    for (int k = 0; k < DIM; k++) {
        float4 b0 = *(const float4*)(BP + k*BST);
        float4 b1 = *(const float4*)(BP + k*BST + 4);
        float4 a0 = *(const float4*)(AP + k*AST);
        float4 a1 = *(const float4*)(AP + k*AST + 4);
        unsigned long long bb[4];
        bb[0] = pack2(b0.x, b0.y);
        bb[1] = pack2(b0.z, b0.w);
        bb[2] = pack2(b1.x, b1.y);
        bb[3] = pack2(b1.z, b1.w);
        float a[8] = {a0.x,a0.y,a0.z,a0.w,a1.x,a1.y,a1.z,a1.w};
        #pragma unroll
        for (int r = 0; r < 8; r++) {
            unsigned long long ar = dup2(a[r]);
            #pragma unroll
            for (int c = 0; c < 4; c++)
                fma2(acc2[r][c], ar, bb[c]);
        }
    }
    __syncthreads();   // FMAs done reading Bsh; reuse as stage [m][n] stride BST

    float* Stg = Bsh;
    #pragma unroll
    for (int r = 0; r < 8; r++) {
        float v0,v1,v2,v3,v4,v5,v6,v7;
        unpack2(acc2[r][0], v0, v1);
        unpack2(acc2[r][1], v2, v3);
        unpack2(acc2[r][2], v4, v5);
        unpack2(acc2[r][3], v6, v7);
        float* p = Stg + (tyc*8+r)*BST + txc*8;
        *(float4*)p       = make_float4(v0,v1,v2,v3);
        *(float4*)(p + 4) = make_float4(v4,v5,v6,v7);
    }
    __syncthreads();

    int w = tid >> 5;        // warp 0..7
    int lane = tid & 31;

    // direct scan: rows of bi, cols of bj (ascending) -> bucket (row, bj)
    for (int rr = 0; rr < 16; rr++) {
        int m = w*16 + rr;
        int ig = row0 + m;
        int c = 0;
        int bucket = ig*NB + bj;
        int base = bucket*CAP;
        #pragma unroll
        for (int p = 0; p < 4; p++) {
            int n = p*32 + lane;
            float v = Stg[m*BST + n];
            int j = col0 + n;
            bool pr = (v > COS_THRESH) && (j != ig);
            if (pr) {
                unsigned lin = (unsigned)ig * N_USERS + (unsigned)j;
                if ((g_excl[lin >> 5] >> (lin & 31u)) & 1u) pr = false;
            }
            unsigned msk = __ballot_sync(0xffffffffu, pr);
            if (pr) {
                int pos = c + __popc(msk & ((1u << lane) - 1u));
                if (pos < CAP) { g_cjbuf[base + pos] = j; g_cvbuf[base + pos] = v; }
            }
            c += __popc(msk);
        }
        if (lane == 0) g_cnt[bucket] = c < CAP ? c : CAP;
    }

    // mirror scan (off-diagonal only): rows of bj, cols of bi -> bucket (row, bi)
    if (bi < bj) {
        for (int rr = 0; rr < 16; rr++) {
            int nn = w*16 + rr;
            int ig = col0 + nn;          // mirror row index
            int c = 0;
            int bucket = ig*NB + bi;
            int base = bucket*CAP;
            #pragma unroll
            for (int p = 0; p < 4; p++) {
                int m = p*32 + lane;
                float v = Stg[m*BST + nn];
                int j = row0 + m;        // mirror col index
                bool pr = (v > COS_THRESH);
                if (pr) {
                    unsigned lin = (unsigned)ig * N_USERS + (unsigned)j;
                    if ((g_excl[lin >> 5] >> (lin & 31u)) & 1u) pr = false;
                }
                unsigned msk = __ballot_sync(0xffffffffu, pr);
                if (pr) {
                    int pos = c + __popc(msk & ((1u << lane) - 1u));
                    if (pos < CAP) { g_cjbuf[base + pos] = j; g_cvbuf[base + pos] = v; }
                }
                c += __popc(msk);
            }
            if (lane == 0) g_cnt[bucket] = c < CAP ? c : CAP;
        }
    }
}

// ---------------- hierarchical prefix scan over 524288 counts ----------------
__global__ void k_scanA() {          // 512 blocks x 256 threads, 4 counts/thread
    __shared__ int sh[256];
    int t = threadIdx.x;
    int base = blockIdx.x*1024 + t*4;
    int s = g_cnt[base] + g_cnt[base+1] + g_cnt[base+2] + g_cnt[base+3];
    #pragma unroll
    for (int o = 16; o; o >>= 1) s += __shfl_down_sync(0xffffffffu, s, o);
    if ((t & 31) == 0) sh[t >> 5] = s;
    __syncthreads();
    if (t == 0) {
        int tot = 0;
        for (int i = 0; i < 8; i++) tot += sh[i];
        g_part[blockIdx.x] = tot;
    }
}

__global__ void k_scanB() {          // 1 block, 512 threads: exclusive scan of partials
    __shared__ int sh[512];
    int t = threadIdx.x;
    sh[t] = g_part[t];
    __syncthreads();
    for (int d = 1; d < 512; d <<= 1) {
        int v = (t >= d) ? sh[t-d] : 0;
        __syncthreads();
        sh[t] += v;
        __syncthreads();
    }
    g_part[t] = (t == 0) ? 0 : sh[t-1];
}

// ---------------- emit candidates in global row-major order ----------------
__global__ void k_emit() {           // 512 blocks x 256 threads, 4 buckets/thread
    __shared__ int sh[256];
    int t = threadIdx.x;
    int base = blockIdx.x*1024 + t*4;
    int c0 = g_cnt[base], c1 = g_cnt[base+1], c2 = g_cnt[base+2], c3 = g_cnt[base+3];
    int mysum = c0 + c1 + c2 + c3;
    sh[t] = mysum;
    __syncthreads();
    for (int d = 1; d < 256; d <<= 1) {
        int v = (t >= d) ? sh[t-d] : 0;
        __syncthreads();
        sh[t] += v;
        __syncthreads();
    }
    int off = g_part[blockIdx.x] + sh[t] - mysum;
    int cs[4] = {c0, c1, c2, c3};
    #pragma unroll
    for (int q = 0; q < 4; q++) {
        int bk = base + q;
        int i = bk >> 6;                 // bucket row
        int bbase = bk * CAP;
        for (int s = 0; s < cs[q]; s++) {
            if (off < K_CAND) {
                g_ci[off] = i;
                g_cj[off] = g_cjbuf[bbase + s];
                g_cv[off] = g_cvbuf[bbase + s];
            }
            off++;
        }
    }
}

// ---------------- gumbel gate + outputs ----------------
__global__ void k_final(const int* __restrict__ nz, const float* __restrict__ gn,
                        const float* __restrict__ bvec, float* __restrict__ out) {
    int t = blockIdx.x * blockDim.x + threadIdx.x;
    if (t >= TOT) return;
    int i, j; float wgt;
    if (t < E_PAIRS) {
        i = nz[2*t]; j = nz[2*t+1]; wgt = 1.0f;
    } else {
        int c = t - E_PAIRS;
        i = g_ci[c]; j = g_cj[c];
        wgt = fmaxf(g_cv[c], 0.0f);
    }
    float l0 = g_AB[i*4+0] + g_AB[j*4+2] + bvec[0];
    float l1 = g_AB[i*4+1] + g_AB[j*4+3] + bvec[1];
    float z0 = (l0 + gn[2*t])   / TAU_F;
    float z1 = (l1 + gn[2*t+1]) / TAU_F;
    float mx = fmaxf(z0, z1);
    float e0 = expf(z0 - mx), e1 = expf(z1 - mx);
    float s0 = e0 / (e0 + e1);
    float h0 = (z1 > z0) ? 0.0f : 1.0f;      // argmax ties -> index 0
    float r = (h0 + s0) - s0;                // straight-through forward value
    float w = r * wgt;

    out[t]          = w;                     // gumbel_01
    out[TOT + t]    = w;                     // gumbel_retain_w[0:TOT]
    out[2*TOT + t]  = w;                     // gumbel_retain_w[TOT:2*TOT]
    out[3*TOT + 2*t]     = (float)i;         // pair_idx
    out[3*TOT + 2*t + 1] = (float)j;
}

// ---------------- launcher ----------------
extern "C" void kernel_launch(void* const* d_in, const int* in_sizes, int n_in,
                              void* d_out, int out_size) {
    const float* emb = (const float*)d_in[0];   // user_emb (8192,128)
    const float* W   = (const float*)d_in[1];   // W (2,256)
    const float* b   = (const float*)d_in[2];   // b (2,)
    const float* gn  = (const float*)d_in[3];   // gumbel_noise (393216,2)
    const int*   nz  = (const int*)d_in[4];     // nonzero_idx (262144,2)
    float* out = (float*)d_out;

    cudaFuncSetAttribute(k_gemm, cudaFuncAttributeMaxDynamicSharedMemorySize, SMEM_BYTES);

    k_clear  <<<2048, 256>>>();
    k_setbits<<<(E_PAIRS+255)/256, 256>>>(nz);
    k_prep   <<<N_USERS, 128>>>(emb, W);
    k_fill   <<<(K_CAND+255)/256, 256>>>();
    k_gemm   <<<NPAIR, 256, SMEM_BYTES>>>();
    k_scanA  <<<512, 256>>>();
    k_scanB  <<<1, 512>>>();
    k_emit   <<<512, 256>>>();
    k_final  <<<(TOT+255)/256, 256>>>(nz, gn, b, out);
}

// round 4
// speedup vs baseline: 3.2325x; 1.8766x over previous
#include <cuda_runtime.h>
#include <cuda_bf16.h>
#include <cstdint>

#define N_USERS 8192
#define DIM 128
#define E_PAIRS 262144
#define K_CAND 131072
#define TOT (E_PAIRS + K_CAND)   /* 393216 */
#define COS_THRESH 0.3f
#define TAU_F 0.2f
#define THR_LOW 0.295f           /* hard bf16 rounding bound is ~0.0039 */

#define TILE 128
#define NB (N_USERS / TILE)          /* 64 */
#define NBUK (N_USERS * NB)          /* 524288 buckets */
#define CAP 16

#define AST 136                      /* bf16 units per staged row (272 B) */
#define CST 132                      /* f32 stage stride */
#define SM_BYTES (2 * TILE * AST * 2)    /* 69632; C reuse needs 67584 */

// ---- device scratch (static; no allocations allowed) ----
__device__ float    g_u[N_USERS*DIM];                  // normalized fp32 (4MB)
__device__ __align__(16) __nv_bfloat16 g_ubf[N_USERS*DIM];  // normalized bf16 (2MB)
__device__ float    g_AB[N_USERS*4];
__device__ unsigned g_excl[N_USERS*N_USERS/32];        // exclusion bitmap (8MB)
__device__ int      g_cnt[NBUK];
__device__ int      g_part[512];
__device__ int      g_cjbuf[NBUK*CAP];                 // 32MB
__device__ float    g_cvbuf[NBUK*CAP];                 // 32MB
__device__ int      g_ci[K_CAND];
__device__ int      g_cj[K_CAND];
__device__ float    g_cv[K_CAND];

// ================= warp-MMA helpers (arch-agnostic PTX) =================
__device__ __forceinline__ uint32_t smem_u32(const void* p) {
    uint32_t a;
    asm("{ .reg .u64 t; cvta.to.shared.u64 t, %1; cvt.u32.u64 %0, t; }" : "=r"(a) : "l"(p));
    return a;
}

#define LDSM_X4(r0, r1, r2, r3, addr) \
    asm volatile("ldmatrix.sync.aligned.m8n8.x4.shared.b16 {%0,%1,%2,%3}, [%4];" \
                 : "=r"(r0), "=r"(r1), "=r"(r2), "=r"(r3) : "r"(addr))

#define MMA_BF16(c, a0, a1, a2, a3, b0, b1) \
    asm volatile("mma.sync.aligned.m16n8k16.row.col.f32.bf16.bf16.f32 " \
                 "{%0,%1,%2,%3}, {%4,%5,%6,%7}, {%8,%9}, {%0,%1,%2,%3};" \
                 : "+f"((c)[0]), "+f"((c)[1]), "+f"((c)[2]), "+f"((c)[3]) \
                 : "r"(a0), "r"(a1), "r"(a2), "r"(a3), "r"(b0), "r"(b1))

// ================= small kernels =================
__global__ void k_clear() {
    int idx = blockIdx.x * blockDim.x + threadIdx.x;
    int stride = gridDim.x * blockDim.x;
    for (int i = idx; i < N_USERS*N_USERS/32; i += stride) g_excl[i] = 0u;
}

__global__ void k_setbits(const int* __restrict__ nz) {
    int t = blockIdx.x * blockDim.x + threadIdx.x;
    if (t < E_PAIRS) {
        int i = nz[2*t];
        int j = nz[2*t+1];
        unsigned lin = (unsigned)i * N_USERS + (unsigned)j;
        atomicOr(&g_excl[lin >> 5], 1u << (lin & 31u));
    }
}

__device__ __forceinline__ float blockSum128(float v) {
    __shared__ float sh[4];
    __syncthreads();
    #pragma unroll
    for (int o = 16; o; o >>= 1) v += __shfl_down_sync(0xffffffffu, v, o);
    if ((threadIdx.x & 31) == 0) sh[threadIdx.x >> 5] = v;
    __syncthreads();
    return sh[0] + sh[1] + sh[2] + sh[3];
}

__global__ void k_prep(const float* __restrict__ emb, const float* __restrict__ W) {
    int row = blockIdx.x;
    int t = threadIdx.x;             // 0..127
    float e = emb[row*DIM + t];

    float sumsq = blockSum128(e*e);
    float nrm = __fsqrt_rn(sumsq);
    float den = fmaxf(nrm, 1e-12f);
    float u = __fdiv_rn(e, den);
    g_u[row*DIM + t] = u;
    g_ubf[row*DIM + t] = __float2bfloat16(u);

    float a0 = blockSum128(e * W[0*256 + t]);
    float a1 = blockSum128(e * W[1*256 + t]);
    float b0 = blockSum128(e * W[0*256 + 128 + t]);
    float b1 = blockSum128(e * W[1*256 + 128 + t]);
    if (t == 0) {
        g_AB[row*4+0] = a0;
        g_AB[row*4+1] = a1;
        g_AB[row*4+2] = b0;
        g_AB[row*4+3] = b1;
    }
}

__global__ void k_fill() {
    int t = blockIdx.x * blockDim.x + threadIdx.x;
    if (t < K_CAND) { g_ci[t] = 0; g_cj[t] = 0; g_cv[t] = -1.0f; }
}

// ================= HMMA bf16 filter GEMM + exact rescore =================
// One CTA per 128x128 tile; 4096 CTAs; 256 threads (8 warps), warp = 16-row strip.
__global__ void __launch_bounds__(256) k_mma() {
    extern __shared__ __align__(16) char smem[];
    __nv_bfloat16* Asm = (__nv_bfloat16*)smem;               // [128][AST]
    __nv_bfloat16* Bsm = Asm + TILE*AST;                     // [128][AST]
    float* Csm = (float*)smem;                               // reuse: [128][CST]

    uint32_t sa = smem_u32(Asm);
    uint32_t sbb = smem_u32(Bsm);

    int tid = threadIdx.x;
    int w = tid >> 5;
    int lane = tid & 31;
    int bi = blockIdx.x >> 6;
    int bj = blockIdx.x & 63;
    int row0 = bi * TILE;
    int col0 = bj * TILE;

    // ---- stage tiles: thread t loads half-row (64 bf16 = 8 x uint4) ----
    {
        int m = tid >> 1;
        int h = tid & 1;
        const uint4* Ag = (const uint4*)(g_ubf + (size_t)(row0 + m) * DIM) + h*8;
        const uint4* Bg = (const uint4*)(g_ubf + (size_t)(col0 + m) * DIM) + h*8;
        uint4* As4 = (uint4*)((char*)Asm + m*272 + h*128);
        uint4* Bs4 = (uint4*)((char*)Bsm + m*272 + h*128);
        #pragma unroll
        for (int g = 0; g < 8; g++) { As4[g] = Ag[g]; Bs4[g] = Bg[g]; }
    }
    __syncthreads();

    // ---- warp MMA: rows m0..m0+15, all 128 cols ----
    int m0 = w * 16;
    float c[16][4];
    #pragma unroll
    for (int nb = 0; nb < 16; nb++)
        #pragma unroll
        for (int q = 0; q < 4; q++) c[nb][q] = 0.0f;

    // A frag addr: lane -> row m0+(lane&15), k-byte off (lane>>4)*16
    uint32_t a_addr = sa + (uint32_t)(m0 + (lane & 15))*272 + (uint32_t)(lane >> 4)*16;
    // B frag addr: nb-pair p covers n rows p*16..p*16+15
    int bl = (lane & 7) + ((lane & 16) ? 8 : 0);
    uint32_t b_addr = sbb + (uint32_t)bl*272 + (uint32_t)((lane & 8) ? 16 : 0);

    #pragma unroll
    for (int kk = 0; kk < 8; kk++) {
        uint32_t a0, a1, a2, a3;
        LDSM_X4(a0, a1, a2, a3, a_addr + kk*32);
        #pragma unroll
        for (int p = 0; p < 8; p++) {
            uint32_t b0, b1, b2, b3;
            LDSM_X4(b0, b1, b2, b3, b_addr + (uint32_t)p*16*272 + kk*32);
            MMA_BF16(c[2*p],   a0, a1, a2, a3, b0, b1);
            MMA_BF16(c[2*p+1], a0, a1, a2, a3, b2, b3);
        }
    }
    __syncthreads();   // all ldmatrix done; safe to overwrite staging with C

    // ---- store fragments to smem C [128][CST] ----
    {
        int g = lane >> 2;
        int t4 = lane & 3;
        #pragma unroll
        for (int nb = 0; nb < 16; nb++) {
            int col = nb*8 + 2*t4;
            *(float2*)&Csm[(m0 + g)*CST + col]     = make_float2(c[nb][0], c[nb][1]);
            *(float2*)&Csm[(m0 + g + 8)*CST + col] = make_float2(c[nb][2], c[nb][3]);
        }
    }
    __syncthreads();

    // ---- ordered scan + exact rescore: warp w owns rows w*16..w*16+15 ----
    for (int rr = 0; rr < 16; rr++) {
        int m = w*16 + rr;
        int ig = row0 + m;
        const float4* ui = (const float4*)(g_u + (size_t)ig * DIM);
        int bucket = ig * NB + bj;
        int base = bucket * CAP;
        int cnt = 0;
        #pragma unroll
        for (int p = 0; p < 4; p++) {
            int n = p*32 + lane;
            float v = Csm[m*CST + n];
            int j = col0 + n;
            bool pr = false;
            float keep = 0.0f;
            if (v > THR_LOW && j != ig) {
                unsigned lin = (unsigned)ig * N_USERS + (unsigned)j;
                if (!((g_excl[lin >> 5] >> (lin & 31u)) & 1u)) {
                    // exact fp32 rescore, strict sequential chain (matches rounds 1-2)
                    const float4* uj = (const float4*)(g_u + (size_t)j * DIM);
                    float acc = 0.0f;
                    #pragma unroll
                    for (int k = 0; k < 32; k++) {
                        float4 a = ui[k];
                        float4 b = uj[k];
                        acc = fmaf(a.x, b.x, acc);
                        acc = fmaf(a.y, b.y, acc);
                        acc = fmaf(a.z, b.z, acc);
                        acc = fmaf(a.w, b.w, acc);
                    }
                    if (acc > COS_THRESH) { pr = true; keep = acc; }
                }
            }
            unsigned msk = __ballot_sync(0xffffffffu, pr);
            if (pr) {
                int pos = cnt + __popc(msk & ((1u << lane) - 1u));
                if (pos < CAP) { g_cjbuf[base + pos] = j; g_cvbuf[base + pos] = keep; }
            }
            cnt += __popc(msk);
        }
        if (lane == 0) g_cnt[bucket] = cnt < CAP ? cnt : CAP;
    }
}

// ================= hierarchical prefix scan over 524288 counts =================
__global__ void k_scanA() {          // 512 blocks x 256 threads, 4 counts/thread
    __shared__ int sh[256];
    int t = threadIdx.x;
    int base = blockIdx.x*1024 + t*4;
    int s = g_cnt[base] + g_cnt[base+1] + g_cnt[base+2] + g_cnt[base+3];
    #pragma unroll
    for (int o = 16; o; o >>= 1) s += __shfl_down_sync(0xffffffffu, s, o);
    if ((t & 31) == 0) sh[t >> 5] = s;
    __syncthreads();
    if (t == 0) {
        int tot = 0;
        for (int i = 0; i < 8; i++) tot += sh[i];
        g_part[blockIdx.x] = tot;
    }
}

__global__ void k_scanB() {          // 1 block, 512 threads
    __shared__ int sh[512];
    int t = threadIdx.x;
    sh[t] = g_part[t];
    __syncthreads();
    for (int d = 1; d < 512; d <<= 1) {
        int v = (t >= d) ? sh[t-d] : 0;
        __syncthreads();
        sh[t] += v;
        __syncthreads();
    }
    g_part[t] = (t == 0) ? 0 : sh[t-1];
}

__global__ void k_emit() {           // 512 blocks x 256 threads, 4 buckets/thread
    __shared__ int sh[256];
    int t = threadIdx.x;
    int base = blockIdx.x*1024 + t*4;
    int c0 = g_cnt[base], c1 = g_cnt[base+1], c2 = g_cnt[base+2], c3 = g_cnt[base+3];
    int mysum = c0 + c1 + c2 + c3;
    sh[t] = mysum;
    __syncthreads();
    for (int d = 1; d < 256; d <<= 1) {
        int v = (t >= d) ? sh[t-d] : 0;
        __syncthreads();
        sh[t] += v;
        __syncthreads();
    }
    int off = g_part[blockIdx.x] + sh[t] - mysum;
    int cs[4] = {c0, c1, c2, c3};
    #pragma unroll
    for (int q = 0; q < 4; q++) {
        int bk = base + q;
        int i = bk >> 6;                 // bucket row (NB = 64)
        int bbase = bk * CAP;
        for (int s = 0; s < cs[q]; s++) {
            if (off < K_CAND) {
                g_ci[off] = i;
                g_cj[off] = g_cjbuf[bbase + s];
                g_cv[off] = g_cvbuf[bbase + s];
            }
            off++;
        }
    }
}

// ================= gumbel gate + outputs =================
__global__ void k_final(const int* __restrict__ nz, const float* __restrict__ gn,
                        const float* __restrict__ bvec, float* __restrict__ out) {
    int t = blockIdx.x * blockDim.x + threadIdx.x;
    if (t >= TOT) return;
    int i, j; float wgt;
    if (t < E_PAIRS) {
        i = nz[2*t]; j = nz[2*t+1]; wgt = 1.0f;
    } else {
        int c = t - E_PAIRS;
        i = g_ci[c]; j = g_cj[c];
        wgt = fmaxf(g_cv[c], 0.0f);
    }
    float l0 = g_AB[i*4+0] + g_AB[j*4+2] + bvec[0];
    float l1 = g_AB[i*4+1] + g_AB[j*4+3] + bvec[1];
    float z0 = (l0 + gn[2*t])   / TAU_F;
    float z1 = (l1 + gn[2*t+1]) / TAU_F;
    float mx = fmaxf(z0, z1);
    float e0 = expf(z0 - mx), e1 = expf(z1 - mx);
    float s0 = e0 / (e0 + e1);
    float h0 = (z1 > z0) ? 0.0f : 1.0f;      // argmax ties -> index 0
    float r = (h0 + s0) - s0;
    float w = r * wgt;

    out[t]          = w;                     // gumbel_01
    out[TOT + t]    = w;                     // gumbel_retain_w[0:TOT]
    out[2*TOT + t]  = w;                     // gumbel_retain_w[TOT:2*TOT]
    out[3*TOT + 2*t]     = (float)i;         // pair_idx
    out[3*TOT + 2*t + 1] = (float)j;
}

// ================= launcher =================
extern "C" void kernel_launch(void* const* d_in, const int* in_sizes, int n_in,
                              void* d_out, int out_size) {
    const float* emb = (const float*)d_in[0];   // user_emb (8192,128)
    const float* W   = (const float*)d_in[1];   // W (2,256)
    const float* b   = (const float*)d_in[2];   // b (2,)
    const float* gn  = (const float*)d_in[3];   // gumbel_noise (393216,2)
    const int*   nz  = (const int*)d_in[4];     // nonzero_idx (262144,2)
    float* out = (float*)d_out;

    cudaFuncSetAttribute(k_mma, cudaFuncAttributeMaxDynamicSharedMemorySize, SM_BYTES);

    k_clear  <<<2048, 256>>>();
    k_setbits<<<(E_PAIRS+255)/256, 256>>>(nz);
    k_prep   <<<N_USERS, 128>>>(emb, W);
    k_mma    <<<NB*NB, 256, SM_BYTES>>>();
    k_fill   <<<(K_CAND+255)/256, 256>>>();
    k_scanA  <<<512, 256>>>();
    k_scanB  <<<1, 512>>>();
    k_emit   <<<512, 256>>>();
    k_final  <<<(TOT+255)/256, 256>>>(nz, gn, b, out);
}